// round 5
// baseline (speedup 1.0000x reference)
#include <cuda_runtime.h>
#include <cuda_fp16.h>
#include <cstdint>

// Problem constants
#define M_TOKENS   2048
#define IN_FEAT    2048
#define OUT_FEAT   2048
#define TILE_B     16
#define C_BLOCKS   128
#define R_BLOCKS   128
#define K_BLOCKS   32
#define RGROUP     4
#define NGROUPS    (R_BLOCKS / RGROUP)   // 32

// Scratch (allocation-free rule: __device__ globals)
// x packed fp16, fragment-linear: [c (128)][token_group (128)][lane (32)][8 halves]
__device__ __half g_xh[(size_t)C_BLOCKS * (M_TOKENS / 16) * 32 * 8];   // 8 MB
// values packed fp16, B-fragment rows: [r][k][lane (32)][8 halves]
__device__ __half g_vh[(size_t)R_BLOCKS * K_BLOCKS * 32 * 8];          // 2 MB
// per-r-group union plan
__device__ int g_ulist[NGROUPS * C_BLOCKS];
__device__ int g_uplan[NGROUPS * C_BLOCKS];
__device__ int g_ucount[NGROUPS];

// ---------------------------------------------------------------------------
// pack_x: smem-staged transpose. CTA = (token group tg, 16 c-blocks).
// ---------------------------------------------------------------------------
#define XROW 264   // halves per smem row

__global__ __launch_bounds__(256)
void pack_x_kernel(const float* __restrict__ x) {
    __shared__ __align__(16) __half sX[16 * XROW];

    const int tid = threadIdx.x;
    const int tg  = blockIdx.x >> 3;        // token group 0..127
    const int cg  = blockIdx.x & 7;         // c-block group 0..7

    // Phase 1: 16 tokens x 256 floats via float4, fully coalesced
    const float* gx = x + (size_t)(tg * 16) * IN_FEAT + cg * 256;
    #pragma unroll
    for (int i = 0; i < 4; i++) {
        int flat  = i * 256 + tid;          // 0..1023 float4 slots
        int token = flat >> 6;              // 0..15
        int cq    = flat & 63;              // float4 index in row
        float4 v  = *(const float4*)(gx + (size_t)token * IN_FEAT + cq * 4);
        __half2 h0 = __floats2half2_rn(v.x, v.y);
        __half2 h1 = __floats2half2_rn(v.z, v.w);
        *(__half2*)&sX[token * XROW + cq * 4]     = h0;
        *(__half2*)&sX[token * XROW + cq * 4 + 2] = h1;
    }
    __syncthreads();

    // Phase 2: 512 fragments (16 c_local x 32 lanes); each thread does 2.
    #pragma unroll
    for (int f0 = 0; f0 < 2; f0++) {
        int f    = f0 * 256 + tid;
        int lane = f & 31;
        int cl   = f >> 5;
        __half2 h[4];
        #pragma unroll
        for (int p = 0; p < 4; p++) {
            int t  = (p & 1) * 8 + (lane >> 2);
            int jp = (p >> 1) * 4 + (lane & 3);
            h[p] = *(__half2*)&sX[t * XROW + cl * 16 + jp * 2];
        }
        int c = cg * 16 + cl;
        *(uint4*)(g_xh + (((size_t)c * 128 + tg) * 32 + lane) * 8) =
            *reinterpret_cast<uint4*>(h);
    }
}

// ---------------------------------------------------------------------------
// pack_v: one thread per (r,k,lane) -> 16B row holding both n-tiles.
// ---------------------------------------------------------------------------
__global__ __launch_bounds__(256)
void pack_v_kernel(const float* __restrict__ values) {
    int idx = blockIdx.x * blockDim.x + threadIdx.x;
    if (idx >= R_BLOCKS * K_BLOCKS * 32) return;
    int lane = idx & 31;
    int k    = (idx >> 5) & 31;
    int r    = idx >> 10;
    int q    = lane & 3;
    int i    = lane >> 2;
    const float* vp = values + (((size_t)r * K_BLOCKS + k) * TILE_B + i) * TILE_B;
    float2 a0 = *(const float2*)(vp + 2 * q);
    float2 a1 = *(const float2*)(vp + 2 * q + 8);
    const float* vp8 = vp + 8 * TILE_B;
    float2 b0 = *(const float2*)(vp8 + 2 * q);
    float2 b1 = *(const float2*)(vp8 + 2 * q + 8);
    __half2 h[4];
    h[0] = __floats2half2_rn(a0.x, a0.y);
    h[1] = __floats2half2_rn(a1.x, a1.y);
    h[2] = __floats2half2_rn(b0.x, b0.y);
    h[3] = __floats2half2_rn(b1.x, b1.y);
    *(uint4*)(g_vh + (size_t)idx * 8) = *reinterpret_cast<uint4*>(h);
}

// ---------------------------------------------------------------------------
// build_plan: per r-group union of col sets + packed user plan.
// plan[c] byte rl = k index of c in row (4g+rl), or 0xFF if absent.
// ---------------------------------------------------------------------------
__global__ __launch_bounds__(128)
void build_plan_kernel(const int* __restrict__ col) {
    __shared__ int s_cols[RGROUP * K_BLOCKS];
    __shared__ int wsum[4];
    const int g = blockIdx.x;
    const int t = threadIdx.x;          // = candidate c, 0..127

    s_cols[t] = col[g * (RGROUP * K_BLOCKS) + t];
    __syncthreads();

    uint32_t plan = 0xFFFFFFFFu;
    #pragma unroll
    for (int rl = 0; rl < RGROUP; rl++) {
        int kk = 0xFF;
        #pragma unroll 8
        for (int k = 0; k < K_BLOCKS; k++)
            if (s_cols[rl * K_BLOCKS + k] == t) kk = k;
        plan = (plan & ~(0xFFu << (8 * rl))) | ((uint32_t)kk << (8 * rl));
    }
    bool present = (plan != 0xFFFFFFFFu);
    int lane = t & 31, wid = t >> 5;
    unsigned bal = __ballot_sync(0xFFFFFFFFu, present);
    if (lane == 0) wsum[wid] = __popc(bal);
    __syncthreads();
    int off = 0;
    for (int i = 0; i < wid; i++) off += wsum[i];
    int pos = off + __popc(bal & ((1u << lane) - 1));
    if (present) {
        g_ulist[g * C_BLOCKS + pos] = t;
        g_uplan[g * C_BLOCKS + pos] = (int)plan;
    }
    if (t == 0) g_ucount[g] = wsum[0] + wsum[1] + wsum[2] + wsum[3];
}

// ---------------------------------------------------------------------------
__device__ __forceinline__ void cp_async16(uint32_t saddr, const void* gaddr) {
    asm volatile("cp.async.cg.shared.global [%0], [%1], 16;\n"
                 :: "r"(saddr), "l"(gaddr));
}
__device__ __forceinline__ void cp_commit() {
    asm volatile("cp.async.commit_group;\n");
}
template <int N>
__device__ __forceinline__ void cp_wait() {
    asm volatile("cp.async.wait_group %0;\n" :: "n"(N));
}

__device__ __forceinline__ void mma16816(float* c, const uint4& a, const uint2& b) {
    asm volatile(
        "mma.sync.aligned.m16n8k16.row.col.f32.f16.f16.f32 "
        "{%0,%1,%2,%3}, {%4,%5,%6,%7}, {%8,%9}, {%0,%1,%2,%3};\n"
        : "+f"(c[0]), "+f"(c[1]), "+f"(c[2]), "+f"(c[3])
        : "r"(a.x), "r"(a.y), "r"(a.z), "r"(a.w), "r"(b.x), "r"(b.y));
}

// ---------------------------------------------------------------------------
// Main kernel: CTA = (256-token tile, r-group of 4). grid (8,32), 256 thr.
// Dynamic smem: V[4 rows] 64KB + 3-stage A ring 24KB + plan lists.
// Streams the UNION of the 4 rows' column sets; each slab feeds avg 1.46
// (row,k) users -> A gather traffic cut ~1.46x vs per-row streaming.
// ---------------------------------------------------------------------------
#define STAGES 3
#define SLAB_HALVES (16 * 32 * 8)            // 4096 halves = 8 KB
#define SV_HALVES   (RGROUP * K_BLOCKS * 32 * 8)  // 32768 halves = 64 KB
#define SMEM_MAIN_BYTES (SV_HALVES * 2 + STAGES * SLAB_HALVES * 2 + 2 * C_BLOCKS * 4 + 16)

__global__ __launch_bounds__(256)
void cms_main_kernel(const int* __restrict__ bias_dummy,
                     const float* __restrict__ bias,
                     float* __restrict__ out) {
    extern __shared__ __align__(16) char smem[];
    __half* sV = (__half*)smem;                               // 64 KB
    __half* sA = sV + SV_HALVES;                              // 24 KB
    int*    s_ulist = (int*)(sA + STAGES * SLAB_HALVES);      // 512 B
    int*    s_uplan = s_ulist + C_BLOCKS;                     // 512 B
    int*    s_cnt   = s_uplan + C_BLOCKS;

    const int bx  = blockIdx.x;          // token tile (256 tokens)
    const int g   = blockIdx.y;          // r-group
    const int tid = threadIdx.x;

    // Load plan into smem
    if (tid < C_BLOCKS) {
        s_ulist[tid] = g_ulist[g * C_BLOCKS + tid];
        s_uplan[tid] = g_uplan[g * C_BLOCKS + tid];
    }
    if (tid == 0) *s_cnt = g_ucount[g];
    __syncthreads();
    const int ucount = *s_cnt;

    const uint32_t sv_base = (uint32_t)__cvta_generic_to_shared(sV);
    const uint32_t sa_base = (uint32_t)__cvta_generic_to_shared(sA);

    // G0: V (64KB) + slab0.  G1: slab1.
    {
        const __half* gv = g_vh + (size_t)(g * RGROUP) * (K_BLOCKS * 32 * 8);
        #pragma unroll
        for (int i = 0; i < 16; i++) {
            int chunk = i * 256 + tid;          // 4096 chunks of 16B
            cp_async16(sv_base + chunk * 16, gv + chunk * 8);
        }
        const __half* ga0 = g_xh + ((size_t)s_ulist[0] * 128 + bx * 16) * 256;
        cp_async16(sa_base + tid * 16,        ga0 + tid * 8);
        cp_async16(sa_base + 4096 + tid * 16, ga0 + (tid + 256) * 8);
        cp_commit();
        const __half* ga1 = g_xh + ((size_t)s_ulist[1] * 128 + bx * 16) * 256;
        uint32_t sb1 = sa_base + SLAB_HALVES * 2;
        cp_async16(sb1 + tid * 16,        ga1 + tid * 8);
        cp_async16(sb1 + 4096 + tid * 16, ga1 + (tid + 256) * 8);
        cp_commit();
    }

    float acc[RGROUP][16];
    #pragma unroll
    for (int rl = 0; rl < RGROUP; rl++)
        #pragma unroll
        for (int i = 0; i < 16; i++) acc[rl][i] = 0.0f;

    const int w    = tid >> 5;
    const int lane = tid & 31;

    for (int u = 0; u < ucount; u++) {
        if (u < ucount - 1) cp_wait<1>(); else cp_wait<0>();
        __syncthreads();

        if (u + 2 < ucount) {
            const __half* ga = g_xh + ((size_t)s_ulist[u + 2] * 128 + bx * 16) * 256;
            uint32_t sb = sa_base + ((u + 2) % STAGES) * (SLAB_HALVES * 2);
            cp_async16(sb + tid * 16,        ga + tid * 8);
            cp_async16(sb + 4096 + tid * 16, ga + (tid + 256) * 8);
            cp_commit();
        }

        const __half* Ab = sA + (u % STAGES) * SLAB_HALVES;
        uint4 a0 = *(const uint4*)&Ab[((w * 2 + 0) * 32 + lane) * 8];
        uint4 a1 = *(const uint4*)&Ab[((w * 2 + 1) * 32 + lane) * 8];
        const uint32_t plan = (uint32_t)s_uplan[u];

        #pragma unroll
        for (int rl = 0; rl < RGROUP; rl++) {
            int k = (plan >> (8 * rl)) & 0xFF;
            if (k != 0xFF) {               // warp-uniform branch
                uint4 vb = *(const uint4*)&sV[(((size_t)rl * K_BLOCKS + k) * 32 + lane) * 8];
                uint2 b0 = make_uint2(vb.x, vb.y);
                uint2 b1 = make_uint2(vb.z, vb.w);
                mma16816(acc[rl] + 0,  a0, b0);
                mma16816(acc[rl] + 4,  a0, b1);
                mma16816(acc[rl] + 8,  a1, b0);
                mma16816(acc[rl] + 12, a1, b1);
            }
        }
    }

    // Epilogue: 4 rows
    const int gq = lane & 3;
    const int gr = lane >> 2;
    #pragma unroll
    for (int rl = 0; rl < RGROUP; rl++) {
        int r = g * RGROUP + rl;
        #pragma unroll
        for (int mt = 0; mt < 2; mt++) {
            int token0 = bx * 256 + (w * 2 + mt) * 16;
            #pragma unroll
            for (int nt = 0; nt < 2; nt++) {
                int f = r * TILE_B + nt * 8 + gq * 2;
                float bv0 = bias[f];
                float bv1 = bias[f + 1];
                const float* a = acc[rl] + (mt * 2 + nt) * 4;
                float* o0 = out + (size_t)(token0 + gr) * OUT_FEAT + f;
                o0[0] = a[0] + bv0;
                o0[1] = a[1] + bv1;
                float* o1 = out + (size_t)(token0 + gr + 8) * OUT_FEAT + f;
                o1[0] = a[2] + bv0;
                o1[1] = a[3] + bv1;
            }
        }
    }
    (void)bias_dummy;
}

// ---------------------------------------------------------------------------
extern "C" void kernel_launch(void* const* d_in, const int* in_sizes, int n_in,
                              void* d_out, int out_size) {
    const float* x      = (const float*)d_in[0];
    const float* values = (const float*)d_in[1];
    const int*   col    = (const int*)d_in[2];
    const float* bias   = (const float*)d_in[3];
    float*       out    = (float*)d_out;

    (void)in_sizes; (void)n_in; (void)out_size;

    static bool attr_set = false;
    if (!attr_set) {
        cudaFuncSetAttribute(cms_main_kernel,
                             cudaFuncAttributeMaxDynamicSharedMemorySize,
                             SMEM_MAIN_BYTES);
        attr_set = true;
    }

    pack_x_kernel<<<128 * 8, 256>>>(x);
    pack_v_kernel<<<(R_BLOCKS * K_BLOCKS * 32) / 256, 256>>>(values);
    build_plan_kernel<<<NGROUPS, 128>>>(col);
    cms_main_kernel<<<dim3(M_TOKENS / 256, NGROUPS), 256, SMEM_MAIN_BYTES>>>(
        (const int*)col, bias, out);
}

// round 6
// speedup vs baseline: 1.0381x; 1.0381x over previous
#include <cuda_runtime.h>
#include <cuda_fp16.h>
#include <cstdint>

// Problem constants
#define M_TOKENS   2048
#define IN_FEAT    2048
#define OUT_FEAT   2048
#define TILE_B     16
#define C_BLOCKS   128
#define R_BLOCKS   128
#define K_BLOCKS   32
#define RGROUP     4
#define NGROUPS    (R_BLOCKS / RGROUP)   // 32

// Scratch (allocation-free rule: __device__ globals)
// x packed fp16, fragment-linear: [c (128)][token_group (128)][lane (32)][8 halves]
__device__ __half g_xh[(size_t)C_BLOCKS * (M_TOKENS / 16) * 32 * 8];   // 8 MB
// values packed fp16, B-fragment rows: [r][k][lane (32)][8 halves]
__device__ __half g_vh[(size_t)R_BLOCKS * K_BLOCKS * 32 * 8];          // 2 MB
// per-r-group union plan (padded to 128 entries, pad plan = 0xFFFFFFFF)
__device__ int g_ulist[NGROUPS * C_BLOCKS];
__device__ int g_uplan[NGROUPS * C_BLOCKS];
__device__ int g_ucount[NGROUPS];

// ---------------------------------------------------------------------------
// pack_x: smem-staged transpose. CTA = (token group tg, 16 c-blocks).
// ---------------------------------------------------------------------------
#define XROW 264   // halves per smem row

__global__ __launch_bounds__(256)
void pack_x_kernel(const float* __restrict__ x) {
    __shared__ __align__(16) __half sX[16 * XROW];

    const int tid = threadIdx.x;
    const int tg  = blockIdx.x >> 3;        // token group 0..127
    const int cg  = blockIdx.x & 7;         // c-block group 0..7

    const float* gx = x + (size_t)(tg * 16) * IN_FEAT + cg * 256;
    #pragma unroll
    for (int i = 0; i < 4; i++) {
        int flat  = i * 256 + tid;
        int token = flat >> 6;
        int cq    = flat & 63;
        float4 v  = *(const float4*)(gx + (size_t)token * IN_FEAT + cq * 4);
        *(__half2*)&sX[token * XROW + cq * 4]     = __floats2half2_rn(v.x, v.y);
        *(__half2*)&sX[token * XROW + cq * 4 + 2] = __floats2half2_rn(v.z, v.w);
    }
    __syncthreads();

    #pragma unroll
    for (int f0 = 0; f0 < 2; f0++) {
        int f    = f0 * 256 + tid;
        int lane = f & 31;
        int cl   = f >> 5;
        __half2 h[4];
        #pragma unroll
        for (int p = 0; p < 4; p++) {
            int t  = (p & 1) * 8 + (lane >> 2);
            int jp = (p >> 1) * 4 + (lane & 3);
            h[p] = *(__half2*)&sX[t * XROW + cl * 16 + jp * 2];
        }
        int c = cg * 16 + cl;
        *(uint4*)(g_xh + (((size_t)c * 128 + tg) * 32 + lane) * 8) =
            *reinterpret_cast<uint4*>(h);
    }
}

// ---------------------------------------------------------------------------
// pack_v: one thread per (r,k,lane) -> 16B row holding both n-tiles.
// ---------------------------------------------------------------------------
__global__ __launch_bounds__(256)
void pack_v_kernel(const float* __restrict__ values) {
    int idx = blockIdx.x * blockDim.x + threadIdx.x;
    if (idx >= R_BLOCKS * K_BLOCKS * 32) return;
    int lane = idx & 31;
    int k    = (idx >> 5) & 31;
    int r    = idx >> 10;
    int q    = lane & 3;
    int i    = lane >> 2;
    const float* vp = values + (((size_t)r * K_BLOCKS + k) * TILE_B + i) * TILE_B;
    float2 a0 = *(const float2*)(vp + 2 * q);
    float2 a1 = *(const float2*)(vp + 2 * q + 8);
    const float* vp8 = vp + 8 * TILE_B;
    float2 b0 = *(const float2*)(vp8 + 2 * q);
    float2 b1 = *(const float2*)(vp8 + 2 * q + 8);
    __half2 h[4];
    h[0] = __floats2half2_rn(a0.x, a0.y);
    h[1] = __floats2half2_rn(a1.x, a1.y);
    h[2] = __floats2half2_rn(b0.x, b0.y);
    h[3] = __floats2half2_rn(b1.x, b1.y);
    *(uint4*)(g_vh + (size_t)idx * 8) = *reinterpret_cast<uint4*>(h);
}

// ---------------------------------------------------------------------------
// build_plan: per r-group union of col sets + packed user plan, padded.
// ---------------------------------------------------------------------------
__global__ __launch_bounds__(128)
void build_plan_kernel(const int* __restrict__ col) {
    __shared__ int s_cols[RGROUP * K_BLOCKS];
    __shared__ int wsum[4];
    const int g = blockIdx.x;
    const int t = threadIdx.x;          // candidate c, 0..127

    // defaults (pad entries): valid c=0, plan=all-absent
    g_ulist[g * C_BLOCKS + t] = 0;
    g_uplan[g * C_BLOCKS + t] = (int)0xFFFFFFFFu;
    s_cols[t] = col[g * (RGROUP * K_BLOCKS) + t];
    __syncthreads();

    uint32_t plan = 0xFFFFFFFFu;
    #pragma unroll
    for (int rl = 0; rl < RGROUP; rl++) {
        int kk = 0xFF;
        #pragma unroll 8
        for (int k = 0; k < K_BLOCKS; k++)
            if (s_cols[rl * K_BLOCKS + k] == t) kk = k;
        plan = (plan & ~(0xFFu << (8 * rl))) | ((uint32_t)kk << (8 * rl));
    }
    bool present = (plan != 0xFFFFFFFFu);
    int lane = t & 31, wid = t >> 5;
    unsigned bal = __ballot_sync(0xFFFFFFFFu, present);
    if (lane == 0) wsum[wid] = __popc(bal);
    __syncthreads();
    int off = 0;
    for (int i = 0; i < wid; i++) off += wsum[i];
    int pos = off + __popc(bal & ((1u << lane) - 1));
    if (present) {
        g_ulist[g * C_BLOCKS + pos] = t;
        g_uplan[g * C_BLOCKS + pos] = (int)plan;
    }
    if (t == 0) g_ucount[g] = wsum[0] + wsum[1] + wsum[2] + wsum[3];
}

// ---------------------------------------------------------------------------
__device__ __forceinline__ void cp_async16(uint32_t saddr, const void* gaddr) {
    asm volatile("cp.async.cg.shared.global [%0], [%1], 16;\n"
                 :: "r"(saddr), "l"(gaddr));
}
__device__ __forceinline__ void cp_commit() {
    asm volatile("cp.async.commit_group;\n");
}
template <int N>
__device__ __forceinline__ void cp_wait() {
    asm volatile("cp.async.wait_group %0;\n" :: "n"(N));
}

__device__ __forceinline__ void mma16816(float* c, const uint4& a, const uint2& b) {
    asm volatile(
        "mma.sync.aligned.m16n8k16.row.col.f32.f16.f16.f32 "
        "{%0,%1,%2,%3}, {%4,%5,%6,%7}, {%8,%9}, {%0,%1,%2,%3};\n"
        : "+f"(c[0]), "+f"(c[1]), "+f"(c[2]), "+f"(c[3])
        : "r"(a.x), "r"(a.y), "r"(a.z), "r"(a.w), "r"(b.x), "r"(b.y));
}

__device__ __forceinline__ uint4 ldgA(int c, int tg, int lane) {
    return __ldg((const uint4*)(g_xh + (((size_t)c * 128 + tg) * 32 + lane) * 8));
}

// ---------------------------------------------------------------------------
// Main: CTA = (128-token tile, r-group of 4). grid (16,32)=512, 256 thr.
// Warp w owns token group tg = bx*8 + w. A fragments LDG'd directly from the
// L2-resident packed x (coalesced 512B/warp), register pipeline depth 4.
// V for 4 rows (64 KB) smem-resident. No per-iter syncs.
// ---------------------------------------------------------------------------
#define SV_HALVES   (RGROUP * K_BLOCKS * 32 * 8)   // 32768 halves = 64 KB
#define SMEM_MAIN_BYTES (SV_HALVES * 2 + 2 * C_BLOCKS * 4)

__global__ __launch_bounds__(256, 3)
void cms_main_kernel(const float* __restrict__ bias,
                     float* __restrict__ out) {
    extern __shared__ __align__(16) char smem[];
    __half* sV      = (__half*)smem;                       // 64 KB
    int*    s_ulist = (int*)(sV + SV_HALVES);              // 512 B
    int*    s_uplan = s_ulist + C_BLOCKS;                  // 512 B

    const int bx  = blockIdx.x;          // token tile (128 tokens)
    const int g   = blockIdx.y;          // r-group
    const int tid = threadIdx.x;
    const int w    = tid >> 5;
    const int lane = tid & 31;
    const int tg   = bx * 8 + w;         // this warp's token group

    const int ucount = g_ucount[g];

    // V for 4 rows: 64 KB contiguous via cp.async (overlaps with A prologue)
    const uint32_t sv_base = (uint32_t)__cvta_generic_to_shared(sV);
    const __half* gv = g_vh + (size_t)(g * RGROUP) * (K_BLOCKS * 32 * 8);
    #pragma unroll
    for (int i = 0; i < 16; i++) {
        int chunk = i * 256 + tid;
        cp_async16(sv_base + chunk * 16, gv + chunk * 8);
    }
    cp_commit();

    if (tid < C_BLOCKS) {
        s_ulist[tid] = g_ulist[g * C_BLOCKS + tid];
        s_uplan[tid] = g_uplan[g * C_BLOCKS + tid];
    }
    __syncthreads();

    // A register pipeline, depth 4
    uint4 apipe[4];
    #pragma unroll
    for (int i = 0; i < 4; i++) apipe[i] = ldgA(s_ulist[i], tg, lane);

    float acc[RGROUP][8];
    #pragma unroll
    for (int rl = 0; rl < RGROUP; rl++)
        #pragma unroll
        for (int i = 0; i < 8; i++) acc[rl][i] = 0.0f;

    cp_wait<0>();
    __syncthreads();   // V visible

    const int upad = (ucount + 3) & ~3;
    for (int u0 = 0; u0 < upad; u0 += 4) {
        #pragma unroll
        for (int i = 0; i < 4; i++) {
            const int u = u0 + i;
            uint4 a = apipe[i];
            int nidx = u + 4; if (nidx > 127) nidx = 127;
            apipe[i] = ldgA(s_ulist[nidx], tg, lane);
            const uint32_t plan = (uint32_t)s_uplan[u];
            #pragma unroll
            for (int rl = 0; rl < RGROUP; rl++) {
                int k = (plan >> (8 * rl)) & 0xFF;
                if (k != 0xFF) {     // warp-uniform
                    uint4 vb = *(const uint4*)&sV[(((size_t)rl * K_BLOCKS + k) * 32 + lane) * 8];
                    uint2 b0 = make_uint2(vb.x, vb.y);
                    uint2 b1 = make_uint2(vb.z, vb.w);
                    mma16816(acc[rl] + 0, a, b0);
                    mma16816(acc[rl] + 4, a, b1);
                }
            }
        }
    }

    // Epilogue: 4 rows x 16 tokens per warp
    const int gq = lane & 3;
    const int gr = lane >> 2;
    const int token0 = bx * 128 + w * 16;
    #pragma unroll
    for (int rl = 0; rl < RGROUP; rl++) {
        int r = g * RGROUP + rl;
        #pragma unroll
        for (int nt = 0; nt < 2; nt++) {
            int f = r * TILE_B + nt * 8 + gq * 2;
            float bv0 = bias[f];
            float bv1 = bias[f + 1];
            const float* a = acc[rl] + nt * 4;
            float* o0 = out + (size_t)(token0 + gr) * OUT_FEAT + f;
            o0[0] = a[0] + bv0;
            o0[1] = a[1] + bv1;
            float* o1 = out + (size_t)(token0 + gr + 8) * OUT_FEAT + f;
            o1[0] = a[2] + bv0;
            o1[1] = a[3] + bv1;
        }
    }
}

// ---------------------------------------------------------------------------
extern "C" void kernel_launch(void* const* d_in, const int* in_sizes, int n_in,
                              void* d_out, int out_size) {
    const float* x      = (const float*)d_in[0];
    const float* values = (const float*)d_in[1];
    const int*   col    = (const int*)d_in[2];
    const float* bias   = (const float*)d_in[3];
    float*       out    = (float*)d_out;

    (void)in_sizes; (void)n_in; (void)out_size;

    static bool attr_set = false;
    if (!attr_set) {
        cudaFuncSetAttribute(cms_main_kernel,
                             cudaFuncAttributeMaxDynamicSharedMemorySize,
                             SMEM_MAIN_BYTES);
        attr_set = true;
    }

    pack_x_kernel<<<128 * 8, 256>>>(x);
    pack_v_kernel<<<(R_BLOCKS * K_BLOCKS * 32) / 256, 256>>>(values);
    build_plan_kernel<<<NGROUPS, 128>>>(col);
    cms_main_kernel<<<dim3(16, NGROUPS), 256, SMEM_MAIN_BYTES>>>(bias, out);
}

// round 7
// speedup vs baseline: 1.7241x; 1.6608x over previous
#include <cuda_runtime.h>
#include <cuda_fp16.h>
#include <cstdint>

// Problem constants
#define M_TOKENS   2048
#define IN_FEAT    2048
#define OUT_FEAT   2048
#define TILE_B     16
#define C_BLOCKS   128
#define R_BLOCKS   128
#define K_BLOCKS   32

// Scratch (allocation-free rule: __device__ globals)
// x packed fp16, fragment-linear: [c (128)][token_group (128)][lane (32)][8 halves]
__device__ __half g_xh[(size_t)C_BLOCKS * (M_TOKENS / 16) * 32 * 8];   // 8 MB
// values packed fp16, B-fragment rows: [r][k][lane (32)][8 halves]
__device__ __half g_vh[(size_t)R_BLOCKS * K_BLOCKS * 32 * 8];          // 2 MB

// ---------------------------------------------------------------------------
// pack_x: smem-staged transpose. CTA = (token group tg, 16 c-blocks).
// ---------------------------------------------------------------------------
#define XROW 264   // halves per smem row

__global__ __launch_bounds__(256)
void pack_x_kernel(const float* __restrict__ x) {
    __shared__ __align__(16) __half sX[16 * XROW];

    const int tid = threadIdx.x;
    const int tg  = blockIdx.x >> 3;        // token group 0..127
    const int cg  = blockIdx.x & 7;         // c-block group 0..7

    const float* gx = x + (size_t)(tg * 16) * IN_FEAT + cg * 256;
    #pragma unroll
    for (int i = 0; i < 4; i++) {
        int flat  = i * 256 + tid;
        int token = flat >> 6;
        int cq    = flat & 63;
        float4 v  = *(const float4*)(gx + (size_t)token * IN_FEAT + cq * 4);
        *(__half2*)&sX[token * XROW + cq * 4]     = __floats2half2_rn(v.x, v.y);
        *(__half2*)&sX[token * XROW + cq * 4 + 2] = __floats2half2_rn(v.z, v.w);
    }
    __syncthreads();

    #pragma unroll
    for (int f0 = 0; f0 < 2; f0++) {
        int f    = f0 * 256 + tid;
        int lane = f & 31;
        int cl   = f >> 5;
        __half2 h[4];
        #pragma unroll
        for (int p = 0; p < 4; p++) {
            int t  = (p & 1) * 8 + (lane >> 2);
            int jp = (p >> 1) * 4 + (lane & 3);
            h[p] = *(__half2*)&sX[t * XROW + cl * 16 + jp * 2];
        }
        int c = cg * 16 + cl;
        *(uint4*)(g_xh + (((size_t)c * 128 + tg) * 32 + lane) * 8) =
            *reinterpret_cast<uint4*>(h);
    }
}

// ---------------------------------------------------------------------------
// pack_v: one thread per (r,k,lane) -> 16B row holding both n-tiles.
// ---------------------------------------------------------------------------
__global__ __launch_bounds__(256)
void pack_v_kernel(const float* __restrict__ values) {
    int idx = blockIdx.x * blockDim.x + threadIdx.x;
    if (idx >= R_BLOCKS * K_BLOCKS * 32) return;
    int lane = idx & 31;
    int k    = (idx >> 5) & 31;
    int r    = idx >> 10;
    int q    = lane & 3;
    int i    = lane >> 2;
    const float* vp = values + (((size_t)r * K_BLOCKS + k) * TILE_B + i) * TILE_B;
    float2 a0 = *(const float2*)(vp + 2 * q);
    float2 a1 = *(const float2*)(vp + 2 * q + 8);
    const float* vp8 = vp + 8 * TILE_B;
    float2 b0 = *(const float2*)(vp8 + 2 * q);
    float2 b1 = *(const float2*)(vp8 + 2 * q + 8);
    __half2 h[4];
    h[0] = __floats2half2_rn(a0.x, a0.y);
    h[1] = __floats2half2_rn(a1.x, a1.y);
    h[2] = __floats2half2_rn(b0.x, b0.y);
    h[3] = __floats2half2_rn(b1.x, b1.y);
    *(uint4*)(g_vh + (size_t)idx * 8) = *reinterpret_cast<uint4*>(h);
}

// ---------------------------------------------------------------------------
__device__ __forceinline__ void cp_async16(uint32_t saddr, const void* gaddr) {
    asm volatile("cp.async.cg.shared.global [%0], [%1], 16;\n"
                 :: "r"(saddr), "l"(gaddr));
}
__device__ __forceinline__ void cp_commit() {
    asm volatile("cp.async.commit_group;\n");
}
template <int N>
__device__ __forceinline__ void cp_wait() {
    asm volatile("cp.async.wait_group %0;\n" :: "n"(N));
}

__device__ __forceinline__ void mma16816(float* c, const uint4& a, const uint2& b) {
    asm volatile(
        "mma.sync.aligned.m16n8k16.row.col.f32.f16.f16.f32 "
        "{%0,%1,%2,%3}, {%4,%5,%6,%7}, {%8,%9}, {%0,%1,%2,%3};\n"
        : "+f"(c[0]), "+f"(c[1]), "+f"(c[2]), "+f"(c[3])
        : "r"(a.x), "r"(a.y), "r"(a.z), "r"(a.w), "r"(b.x), "r"(b.y));
}

__device__ __forceinline__ uint4 ldgA(int c, int tg, int lane) {
    return __ldg((const uint4*)(g_xh + (((size_t)c * 128 + tg) * 32 + lane) * 8));
}

// ---------------------------------------------------------------------------
// Main: CTA = (256-token tile, one r). grid (8,128)=1024, 256 thr.
// Warp w owns token groups tg0 = bx*16 + 2w, tg0+1. A fragments LDG'd
// directly from L2-resident packed x (coalesced 512B/warp), register
// pipeline depth 2. V[r] (16 KB) smem-resident. Zero syncs in the k-loop.
// ---------------------------------------------------------------------------
#define SV_HALVES (K_BLOCKS * 32 * 8)    // 8192 halves = 16 KB

__global__ __launch_bounds__(256, 4)
void cms_main_kernel(const int* __restrict__ col_indices,
                     const float* __restrict__ bias,
                     float* __restrict__ out) {
    __shared__ __align__(16) __half sV[SV_HALVES];   // 16 KB
    __shared__ int s_col[K_BLOCKS + 2];              // padded for prefetch clamp

    const int bx   = blockIdx.x;          // token tile (256 tokens)
    const int r    = blockIdx.y;
    const int tid  = threadIdx.x;
    const int w    = tid >> 5;
    const int lane = tid & 31;
    const int tg0  = bx * 16 + w * 2;

    if (tid < K_BLOCKS) s_col[tid] = col_indices[r * K_BLOCKS + tid];
    if (tid < 2)        s_col[K_BLOCKS + tid] = col_indices[r * K_BLOCKS + K_BLOCKS - 1];

    // V[r]: 16 KB contiguous via cp.async
    const uint32_t sv_base = (uint32_t)__cvta_generic_to_shared(sV);
    const __half* gv = g_vh + (size_t)r * SV_HALVES;
    #pragma unroll
    for (int i = 0; i < 4; i++) {
        int chunk = i * 256 + tid;
        cp_async16(sv_base + chunk * 16, gv + chunk * 8);
    }
    cp_commit();
    __syncthreads();   // s_col visible

    // A register pipeline, depth 2, for 2 token groups
    uint4 ap0[2], ap1[2];
    {
        int c0 = s_col[0], c1 = s_col[1];
        ap0[0] = ldgA(c0, tg0, lane);     ap1[0] = ldgA(c0, tg0 + 1, lane);
        ap0[1] = ldgA(c1, tg0, lane);     ap1[1] = ldgA(c1, tg0 + 1, lane);
    }

    float acc[2][8];
    #pragma unroll
    for (int mt = 0; mt < 2; mt++)
        #pragma unroll
        for (int i = 0; i < 8; i++) acc[mt][i] = 0.0f;

    cp_wait<0>();
    __syncthreads();   // V visible

    #pragma unroll 4
    for (int k = 0; k < K_BLOCKS; k++) {
        uint4 a0 = ap0[k & 1];
        uint4 a1 = ap1[k & 1];
        int cn = s_col[k + 2];            // clamped pad beyond 31
        ap0[k & 1] = ldgA(cn, tg0, lane);
        ap1[k & 1] = ldgA(cn, tg0 + 1, lane);

        uint4 vb = *(const uint4*)&sV[((size_t)k * 32 + lane) * 8];
        uint2 b0 = make_uint2(vb.x, vb.y);
        uint2 b1 = make_uint2(vb.z, vb.w);

        mma16816(acc[0] + 0, a0, b0);
        mma16816(acc[0] + 4, a0, b1);
        mma16816(acc[1] + 0, a1, b0);
        mma16816(acc[1] + 4, a1, b1);
    }

    // Epilogue: 2 token groups x 16 cols
    const int gq = lane & 3;
    const int gr = lane >> 2;
    #pragma unroll
    for (int mt = 0; mt < 2; mt++) {
        int token0 = (tg0 + mt) * 16;
        #pragma unroll
        for (int nt = 0; nt < 2; nt++) {
            int f = r * TILE_B + nt * 8 + gq * 2;
            float bv0 = bias[f];
            float bv1 = bias[f + 1];
            const float* a = acc[mt] + nt * 4;
            float* o0 = out + (size_t)(token0 + gr) * OUT_FEAT + f;
            o0[0] = a[0] + bv0;
            o0[1] = a[1] + bv1;
            float* o1 = out + (size_t)(token0 + gr + 8) * OUT_FEAT + f;
            o1[0] = a[2] + bv0;
            o1[1] = a[3] + bv1;
        }
    }
}

// ---------------------------------------------------------------------------
extern "C" void kernel_launch(void* const* d_in, const int* in_sizes, int n_in,
                              void* d_out, int out_size) {
    const float* x      = (const float*)d_in[0];
    const float* values = (const float*)d_in[1];
    const int*   col    = (const int*)d_in[2];
    const float* bias   = (const float*)d_in[3];
    float*       out    = (float*)d_out;

    (void)in_sizes; (void)n_in; (void)out_size;

    pack_x_kernel<<<128 * 8, 256>>>(x);
    pack_v_kernel<<<(R_BLOCKS * K_BLOCKS * 32) / 256, 256>>>(values);
    cms_main_kernel<<<dim3(M_TOKENS / 256, R_BLOCKS), 256>>>(col, bias, out);
}